// round 7
// baseline (speedup 1.0000x reference)
#include <cuda_runtime.h>
#include <math.h>

typedef unsigned long long u64;

// Problem shape (fixed): B=2, S=8, N=2048, D=3
#define NPTS   2048
#define TPB    128
#define SPLIT  4                    // DB split across lanes of a group
#define QPT    4                    // queries per thread
#define QPB    ((TPB / SPLIT) * QPT) // 128 queries per block
#define CHUNKS (NPTS / QPB)         // 16
#define NSETS  16                   // B*S
#define NBLK   (NSETS * 2 * CHUNKS) // 512 blocks -> single wave

#define NJP    (NPTS / 2)           // 1024 lane-pairs total
#define QJP    (NJP / SPLIT)        // 256 lane-pairs per quarter
#define QPAD   (QJP + 1)            // quarters offset by 4 banks

#define LOC_MASK 0xFFu              // 8 bits: loc within quarter
#define LKEY_MASK 0xFFFFFF00u       // in-loop distance mask
#define IDX_MASK 0x7FFu             // 11 bits for full j
#define KEY_MASK 0xFFFFF800u        // post-loop distance mask

__device__ float g_loss_part[NBLK];
__device__ float g_cent_part[NBLK][3];
__device__ unsigned int g_ctr = 0;   // self-resetting completion counter

__device__ __forceinline__ float smooth_l1(float a, float b) {
    float d = fabsf(a - b);
    return (d < 1.0f) ? (0.5f * d * d) : (d - 0.5f);
}

// Blackwell packed f32x2 FMA (only reachable via PTX)
#define FMA2(d, a, b, c) \
    asm("fma.rn.f32x2 %0, %1, %2, %3;" : "=l"(d) : "l"(a), "l"(b), "l"(c))
#define PACK2(d, lo, hi) \
    asm("mov.b64 %0, {%1, %2};" : "=l"(d) : "f"(lo), "f"(hi))
#define UNPACK2(lo, hi, s) \
    asm("mov.b64 {%0, %1}, %2;" : "=f"(lo), "=f"(hi) : "l"(s))

__global__ __launch_bounds__(TPB, 4)
void chamfer_kernel(const float* __restrict__ Xv, const float* __restrict__ Tv,
                    const float* __restrict__ w, float* __restrict__ out)
{
    const int tid   = threadIdx.x;
    const int blk   = blockIdx.x;
    const int set   = blk / (2 * CHUNKS);
    const int rem   = blk % (2 * CHUNKS);
    const int dir   = rem / CHUNKS;      // 0: queries=X_v, db=target ; 1: swapped
    const int chunk = rem % CHUNKS;

    const float* __restrict__ qg = (dir == 0 ? Xv : Tv) + set * NPTS * 3;
    const float* __restrict__ dg = (dir == 0 ? Tv : Xv) + set * NPTS * 3;

    // DB tile in quarters, interleaved for f32x2 over consecutive-j pairs.
    // shA[qt][loc] = { (-2x_j, -2x_{j+1}) , (-2y_j, -2y_{j+1}) },  jp = qt*QJP + loc
    // shB[qt][loc] = { (-2z_j, -2z_{j+1}) , ( t2_j,  t2_{j+1}) }
    __shared__ ulonglong2 shA[SPLIT][QPAD];   // ~16.1 KB
    __shared__ ulonglong2 shB[SPLIT][QPAD];   // ~16.1 KB
    __shared__ float4 red4[TPB];              // 2 KB
    __shared__ unsigned int is_last;

    for (int i = tid; i < NPTS; i += TPB) {
        float x = dg[i * 3 + 0];
        float y = dg[i * 3 + 1];
        float z = dg[i * 3 + 2];
        float n = x * x;
        n = fmaf(y, y, n);
        n = fmaf(z, z, n);
        int jp = i >> 1, l = i & 1;
        int qt = jp >> 8, loc = jp & (QJP - 1);
        float* fA = (float*)&shA[qt][loc];
        float* fB = (float*)&shB[qt][loc];
        fA[0 + l] = -2.0f * x;
        fA[2 + l] = -2.0f * y;
        fB[0 + l] = -2.0f * z;
        fB[2 + l] = n;
    }
    __syncthreads();

    // Group g owns QPT queries; this lane's quarter = tid&3.
    const int g  = tid >> 2;             // 0..31
    const int qt = tid & 3;
    u64 qx2[QPT], qy2[QPT], qz2[QPT];
#pragma unroll
    for (int q = 0; q < QPT; q++) {
        int qi = chunk * QPB + q * (QPB / QPT) + g;
        float x = qg[qi * 3 + 0];
        float y = qg[qi * 3 + 1];
        float z = qg[qi * 3 + 2];
        PACK2(qx2[q], x, x);
        PACK2(qy2[q], y, y);
        PACK2(qz2[q], z, z);
    }

    // 2 chains per query (even/odd candidate lane) = 8 independent chains.
    float me[QPT], mo[QPT];
#pragma unroll
    for (int q = 0; q < QPT; q++) { me[q] = 3.0e38f; mo[q] = 3.0e38f; }

    const ulonglong2* __restrict__ pA = shA[qt];
    const ulonglong2* __restrict__ pB = shB[qt];

    // Argmin key: t2_j - 2*q.t_j (p2 constant per query -> dropped).
    // In-loop key embeds ONLY loc (= loop counter): 1 LOP3 + 1 FMNMX per candidate.
#pragma unroll 8
    for (int loc = 0; loc < QJP; loc++) {
        ulonglong2 va = pA[loc];   // {mx2, my2}
        ulonglong2 vb = pB[loc];   // {mz2, t2x2}
#pragma unroll
        for (int q = 0; q < QPT; q++) {
            u64 a = vb.y;
            FMA2(a, qx2[q], va.x, a);
            FMA2(a, qy2[q], va.y, a);
            FMA2(a, qz2[q], vb.x, a);
            float d0, d1;
            UNPACK2(d0, d1, a);
            unsigned k0 = (__float_as_uint(d0) & LKEY_MASK) | (unsigned)loc;
            unsigned k1 = (__float_as_uint(d1) & LKEY_MASK) | (unsigned)loc;
            me[q] = fminf(me[q], __uint_as_float(k0));
            mo[q] = fminf(mo[q], __uint_as_float(k1));
        }
    }

    // Per query: fold chain identity (qt, parity) + loc into full 11-bit j,
    // then merge across the 4-lane group.
    float sl = 0.0f, cx = 0.0f, cy = 0.0f, cz = 0.0f;
    float keyq[QPT];
#pragma unroll
    for (int q = 0; q < QPT; q++) {
        float a = me[q], b = mo[q];
        unsigned par = (b < a) ? 1u : 0u;
        float mk = fminf(a, b);
        unsigned bits = __float_as_uint(mk);
        unsigned loc  = bits & LOC_MASK;
        unsigned jfull = (unsigned)qt * (2u * QJP) + 2u * loc + par;
        float key = __uint_as_float((bits & KEY_MASK) | jfull);
        key = fminf(key, __shfl_xor_sync(0xffffffffu, key, 1));
        key = fminf(key, __shfl_xor_sync(0xffffffffu, key, 2));
        keyq[q] = key;
    }

    if (qt == 0) {
#pragma unroll
        for (int q = 0; q < QPT; q++) {
            int j  = (int)(__float_as_uint(keyq[q]) & IDX_MASK);
            int jp = j >> 1, l = j & 1;
            int qq = jp >> 8, loc = jp & (QJP - 1);
            const float* fA = (const float*)&shA[qq][loc];
            const float* fB = (const float*)&shB[qq][loc];
            float qx, qy, qz, dummy;
            UNPACK2(qx, dummy, qx2[q]);
            UNPACK2(qy, dummy, qy2[q]);
            UNPACK2(qz, dummy, qz2[q]);
            sl += smooth_l1(qx, -0.5f * fA[0 + l]);
            sl += smooth_l1(qy, -0.5f * fA[2 + l]);
            sl += smooth_l1(qz, -0.5f * fB[0 + l]);
            cx += qx; cy += qy; cz += qz;
        }
    }

    // Deterministic block reduction (fixed tree order).
    red4[tid] = make_float4(sl, cx, cy, cz);
    __syncthreads();
    for (int s = TPB / 2; s > 0; s >>= 1) {
        if (tid < s) {
            float4 a = red4[tid];
            float4 b = red4[tid + s];
            red4[tid] = make_float4(a.x + b.x, a.y + b.y, a.z + b.z, a.w + b.w);
        }
        __syncthreads();
    }
    if (tid == 0) {
        float4 r = red4[0];
        g_loss_part[blk]    = r.x;
        g_cent_part[blk][0] = r.y;
        g_cent_part[blk][1] = r.z;
        g_cent_part[blk][2] = r.w;
        __threadfence();
        unsigned int v = atomicAdd(&g_ctr, 1u);
        is_last = (v == NBLK - 1) ? 1u : 0u;
    }
    __syncthreads();

    // Last block finalizes (deterministic; counter self-resets for graph replay).
    if (is_last && tid < 32) {
        __threadfence();
        const int t = tid;
        float lp = 0.0f, lc = 0.0f;
        if (t < NSETS) {
            float s = 0.0f;
            for (int d = 0; d < 2; d++)
                for (int c = 0; c < CHUNKS; c++)
                    s += g_loss_part[(t * 2 + d) * CHUNKS + c];
            lp = s * (1.0f / (float)(NPTS * 3)) * w[t];

            float pc0 = 0, pc1 = 0, pc2 = 0, tc0 = 0, tc1 = 0, tc2 = 0;
            for (int c = 0; c < CHUNKS; c++) {
                int b0 = (t * 2 + 0) * CHUNKS + c;   // dir 0 queries = X_v
                int b1 = (t * 2 + 1) * CHUNKS + c;   // dir 1 queries = target
                pc0 += g_cent_part[b0][0]; pc1 += g_cent_part[b0][1]; pc2 += g_cent_part[b0][2];
                tc0 += g_cent_part[b1][0]; tc1 += g_cent_part[b1][1]; tc2 += g_cent_part[b1][2];
            }
            const float inv_n = 1.0f / (float)NPTS;
            lc += smooth_l1(pc0 * inv_n, tc0 * inv_n);
            lc += smooth_l1(pc1 * inv_n, tc1 * inv_n);
            lc += smooth_l1(pc2 * inv_n, tc2 * inv_n);
        }
#pragma unroll
        for (int o = 16; o > 0; o >>= 1) {
            lp += __shfl_down_sync(0xffffffff, lp, o);
            lc += __shfl_down_sync(0xffffffff, lc, o);
        }
        if (t == 0) {
            out[0] = lp * 0.5f;          // / B
            out[1] = lc * (1.0f / 6.0f); // / (B*3)
            g_ctr = 0;                   // reset for next graph replay
        }
    }
}

extern "C" void kernel_launch(void* const* d_in, const int* in_sizes, int n_in,
                              void* d_out, int out_size) {
    const float* Xv = (const float*)d_in[0];
    const float* Tv = (const float*)d_in[1];
    const float* w  = (const float*)d_in[2];
    float* out = (float*)d_out;

    chamfer_kernel<<<NBLK, TPB>>>(Xv, Tv, w, out);
}